// round 6
// baseline (speedup 1.0000x reference)
#include <cuda_runtime.h>
#include <cuda_bf16.h>
#include <math.h>

namespace {

typedef unsigned int uint;

constexpr int NTOK  = 4801;
constexpr int D     = 512;
constexpr int QKVW  = 1536;
constexpr int FRAMES= 4;
constexpr int NSP   = 1200;
constexpr int HALFN = 600;
constexpr int NKEY  = 601;
constexpr int NHEAD = 8;
constexpr int DH    = 64;
constexpr float ASCALE = 0.125f;
constexpr int FF1   = 4096;
constexpr int FF2   = 2048;
constexpr int NPATCH= 4800;
constexpr int NGRP  = 64;

// fp32 buffers
__device__ float g_x [NTOK * D];
__device__ float g_xn[D];
__device__ float g_S [(size_t)NGRP * HALFN * NKEY];

// packed bf16x2 hi/lo buffers (pair index = dim/2)
__device__ uint g_qvH[NTOK * 768],  g_qvL[NTOK * 768];    // qkv packed
__device__ uint g_hH [NTOK * 2048], g_hL [NTOK * 2048];   // ff1 out packed
__device__ uint g_xnH[NTOK * 256],  g_xnL[NTOK * 256];
__device__ uint g_atH[NTOK * 256],  g_atL[NTOK * 256];
__device__ uint g_acH[NTOK * 1024], g_acL[NTOK * 1024];
__device__ uint g_tkH[NPATCH * 384], g_tkL[NPATCH * 384];

// packed split weights (all 12 layers)
__device__ uint g_wqtH[12 * 256 * QKVW], g_wqtL[12 * 256 * QKVW];
__device__ uint g_wqsH[12 * 256 * QKVW], g_wqsL[12 * 256 * QKVW];
__device__ uint g_wotH[12 * 256 * D],    g_wotL[12 * 256 * D];
__device__ uint g_wosH[12 * 256 * D],    g_wosL[12 * 256 * D];
__device__ uint g_w1H [12 * 256 * FF1],  g_w1L [12 * 256 * FF1];
__device__ uint g_w2H [12 * 1024 * D],   g_w2L [12 * 1024 * D];
__device__ uint g_wpH [384 * D],         g_wpL [384 * D];

__device__ __forceinline__ void split2(float x0, float x1, uint& hi, uint& lo) {
    __nv_bfloat16 h0 = __float2bfloat16(x0);
    __nv_bfloat16 h1 = __float2bfloat16(x1);
    __nv_bfloat16 l0 = __float2bfloat16(x0 - __bfloat162float(h0));
    __nv_bfloat16 l1 = __float2bfloat16(x1 - __bfloat162float(h1));
    __nv_bfloat162 H = __nv_bfloat162(h0, h1);
    __nv_bfloat162 L = __nv_bfloat162(l0, l1);
    hi = *reinterpret_cast<uint*>(&H);
    lo = *reinterpret_cast<uint*>(&L);
}

__device__ __forceinline__ float2 rec2(uint H, uint L) {
    __nv_bfloat162 h = *reinterpret_cast<__nv_bfloat162*>(&H);
    __nv_bfloat162 l = *reinterpret_cast<__nv_bfloat162*>(&L);
    return make_float2(__low2float(h) + __low2float(l), __high2float(h) + __high2float(l));
}

__device__ __forceinline__ float recel(uint H, uint L, int sel) {
    float2 v = rec2(H, L);
    return sel ? v.y : v.x;
}

__device__ __forceinline__ void mma_bf16(float* acc, const uint* a, const uint* b) {
    asm volatile(
        "mma.sync.aligned.m16n8k16.row.col.f32.bf16.bf16.f32 "
        "{%0,%1,%2,%3}, {%4,%5,%6,%7}, {%8,%9}, {%0,%1,%2,%3};"
        : "+f"(acc[0]), "+f"(acc[1]), "+f"(acc[2]), "+f"(acc[3])
        : "r"(a[0]), "r"(a[1]), "r"(a[2]), "r"(a[3]), "r"(b[0]), "r"(b[1]));
}

// ---------------------------------------------------------------- weight split prep
__global__ void split_w_kernel(const float* __restrict__ W, uint* __restrict__ H,
                               uint* __restrict__ L, int N, long long total)
{
    long long idx = (long long)blockIdx.x * blockDim.x + threadIdx.x;
    if (idx >= total) return;
    long long kp = idx / N;
    int n = (int)(idx - kp * N);
    float x0 = W[(size_t)(2 * kp) * N + n];
    float x1 = W[(size_t)(2 * kp + 1) * N + n];
    split2(x0, x1, H[idx], L[idx]);
}

// ---------------------------------------------------------------- split-bf16 GEMM
// C[M,N] = A @ B, K=2*Kp, pre-split operands. PACK: write packed hi/lo pairs along N.
template <bool PACK>
__global__ __launch_bounds__(256)
void bgemm_kernel(const uint* __restrict__ AH, const uint* __restrict__ AL,
                  const uint* __restrict__ BH, const uint* __restrict__ BL,
                  const float* __restrict__ bias, const float* __restrict__ resid,
                  float* __restrict__ C, uint* __restrict__ CH, uint* __restrict__ CL,
                  int M, int N, int Kp)
{
    __shared__ uint AsH[128][20], AsL[128][20];
    __shared__ uint BsH[16][136], BsL[16][136];

    const int tid  = threadIdx.x;
    const int lane = tid & 31;
    const int warp = tid >> 5;
    const int grp  = lane >> 2;
    const int qid  = lane & 3;
    const int wm   = (warp & 1) * 64;
    const int wn   = (warp >> 1) * 32;
    const int row0 = blockIdx.y * 128;
    const int col0 = blockIdx.x * 128;

    float acc[4][4][4];
#pragma unroll
    for (int mt = 0; mt < 4; mt++)
#pragma unroll
        for (int nt = 0; nt < 4; nt++)
#pragma unroll
            for (int e = 0; e < 4; e++) acc[mt][nt][e] = 0.f;

    uint4 aH[2], aL[2], bH[2], bL[2];

    auto gload = [&](int kp0) {
#pragma unroll
        for (int u = 0; u < 2; u++) {
            int idx = tid + u * 256;
            int r = idx >> 2, c4 = idx & 3;
            int gr = row0 + r;
            if (gr < M) {
                aH[u] = *reinterpret_cast<const uint4*>(AH + (size_t)gr * Kp + kp0 + c4 * 4);
                aL[u] = *reinterpret_cast<const uint4*>(AL + (size_t)gr * Kp + kp0 + c4 * 4);
            } else {
                aH[u] = make_uint4(0, 0, 0, 0);
                aL[u] = make_uint4(0, 0, 0, 0);
            }
        }
#pragma unroll
        for (int u = 0; u < 2; u++) {
            int idx = tid + u * 256;
            int kr = idx >> 5, c4 = idx & 31;
            size_t off = (size_t)(kp0 + kr) * N + col0 + c4 * 4;
            bH[u] = *reinterpret_cast<const uint4*>(BH + off);
            bL[u] = *reinterpret_cast<const uint4*>(BL + off);
        }
    };

    auto sstore = [&]() {
#pragma unroll
        for (int u = 0; u < 2; u++) {
            int idx = tid + u * 256;
            int r = idx >> 2, c4 = idx & 3;
            *reinterpret_cast<uint4*>(&AsH[r][c4 * 4]) = aH[u];
            *reinterpret_cast<uint4*>(&AsL[r][c4 * 4]) = aL[u];
        }
#pragma unroll
        for (int u = 0; u < 2; u++) {
            int idx = tid + u * 256;
            int kr = idx >> 5, c4 = idx & 31;
            *reinterpret_cast<uint4*>(&BsH[kr][c4 * 4]) = bH[u];
            *reinterpret_cast<uint4*>(&BsL[kr][c4 * 4]) = bL[u];
        }
    };

    auto compute = [&]() {
#pragma unroll
        for (int kk = 0; kk < 2; kk++) {
            uint bhf[4][2], blf[4][2];
#pragma unroll
            for (int nt = 0; nt < 4; nt++) {
                int c = wn + nt * 8 + grp;
                bhf[nt][0] = BsH[kk * 8 + qid    ][c];
                bhf[nt][1] = BsH[kk * 8 + qid + 4][c];
                blf[nt][0] = BsL[kk * 8 + qid    ][c];
                blf[nt][1] = BsL[kk * 8 + qid + 4][c];
            }
#pragma unroll
            for (int mt = 0; mt < 4; mt++) {
                int r = wm + mt * 16;
                uint ah[4], al[4];
                ah[0] = AsH[r + grp    ][kk * 8 + qid    ];
                ah[1] = AsH[r + grp + 8][kk * 8 + qid    ];
                ah[2] = AsH[r + grp    ][kk * 8 + qid + 4];
                ah[3] = AsH[r + grp + 8][kk * 8 + qid + 4];
                al[0] = AsL[r + grp    ][kk * 8 + qid    ];
                al[1] = AsL[r + grp + 8][kk * 8 + qid    ];
                al[2] = AsL[r + grp    ][kk * 8 + qid + 4];
                al[3] = AsL[r + grp + 8][kk * 8 + qid + 4];
#pragma unroll
                for (int nt = 0; nt < 4; nt++) {
                    mma_bf16(acc[mt][nt], al, bhf[nt]);
                    mma_bf16(acc[mt][nt], ah, blf[nt]);
                    mma_bf16(acc[mt][nt], ah, bhf[nt]);
                }
            }
        }
    };

    gload(0);
    sstore();
    __syncthreads();
    for (int kp0 = 16; kp0 < Kp; kp0 += 16) {
        gload(kp0);
        compute();
        __syncthreads();
        sstore();
        __syncthreads();
    }
    compute();

#pragma unroll
    for (int mt = 0; mt < 4; mt++) {
#pragma unroll
        for (int e2 = 0; e2 < 2; e2++) {
            int gr = row0 + wm + mt * 16 + grp + e2 * 8;
            if (gr >= M) continue;
#pragma unroll
            for (int nt = 0; nt < 4; nt++) {
                int gc = col0 + wn + nt * 8 + qid * 2;
                float v0 = acc[mt][nt][e2 * 2 + 0];
                float v1 = acc[mt][nt][e2 * 2 + 1];
                if (bias)  { v0 += bias[gc]; v1 += bias[gc + 1]; }
                if (PACK) {
                    split2(v0, v1, CH[(size_t)gr * (N >> 1) + (gc >> 1)],
                                   CL[(size_t)gr * (N >> 1) + (gc >> 1)]);
                } else {
                    if (resid) {
                        v0 += resid[(size_t)gr * N + gc];
                        v1 += resid[(size_t)gr * N + gc + 1];
                    }
                    C[(size_t)gr * N + gc]     = v0;
                    C[(size_t)gr * N + gc + 1] = v1;
                }
            }
        }
    }
}

// ---------------------------------------------------------------- patchify (packed split out)
__global__ void patchify_kernel(const float* __restrict__ video,
                                uint* __restrict__ tH, uint* __restrict__ tL)
{
    int idx = blockIdx.x * blockDim.x + threadIdx.x;
    if (idx >= NPATCH * 384) return;
    int t = idx / 384, pp = idx % 384;
    int side = t / 2400;
    int r = t % 2400;
    int f = r / 600;
    int rr = r % 600;
    int ph = rr / 20;
    int pw = rr % 20;
    float v[2];
#pragma unroll
    for (int e = 0; e < 2; e++) {
        int pd = pp * 2 + e;
        int p1 = pd / 48;
        int rem = pd % 48;
        int p2 = rem / 3;
        int c  = rem % 3;
        int row = ph * 16 + p1;
        int col = side * 320 + pw * 16 + p2;
        v[e] = video[(((size_t)f * 3 + c) * 480 + row) * 640 + col];
    }
    split2(v[0], v[1], tH[idx], tL[idx]);
}

__global__ void addpos_kernel(float* __restrict__ x, const float* __restrict__ cls,
                              const float* __restrict__ pos)
{
    int idx = blockIdx.x * blockDim.x + threadIdx.x;
    if (idx >= NTOK * D) return;
    if (idx < D) x[idx] = cls[idx] + pos[idx];
    else         x[idx] += pos[idx];
}

// ---------------------------------------------------------------- LayerNorm (packed out)
__global__ void layernorm_pack_kernel(const float* __restrict__ x, const float* __restrict__ g,
                                      const float* __restrict__ b,
                                      uint* __restrict__ oH, uint* __restrict__ oL)
{
    int row = blockIdx.x;
    int tid = threadIdx.x;  // 256
    const float* xr = x + (size_t)row * D;
    float2 xv = *reinterpret_cast<const float2*>(xr + 2 * tid);
    __shared__ float red[8];

    float s = xv.x + xv.y;
#pragma unroll
    for (int o = 16; o; o >>= 1) s += __shfl_xor_sync(0xffffffffu, s, o);
    if ((tid & 31) == 0) red[tid >> 5] = s;
    __syncthreads();
    if (tid == 0) { float t = 0; for (int i = 0; i < 8; i++) t += red[i]; red[0] = t; }
    __syncthreads();
    float mu = red[0] * (1.f / 512.f);
    __syncthreads();

    float d0 = xv.x - mu, d1 = xv.y - mu;
    float v = d0 * d0 + d1 * d1;
#pragma unroll
    for (int o = 16; o; o >>= 1) v += __shfl_xor_sync(0xffffffffu, v, o);
    if ((tid & 31) == 0) red[tid >> 5] = v;
    __syncthreads();
    if (tid == 0) { float t = 0; for (int i = 0; i < 8; i++) t += red[i]; red[0] = t; }
    __syncthreads();
    float rstd = rsqrtf(red[0] * (1.f / 512.f) + 1e-5f);

    float2 gv = *reinterpret_cast<const float2*>(g + 2 * tid);
    float2 bv = *reinterpret_cast<const float2*>(b + 2 * tid);
    split2(d0 * rstd * gv.x + bv.x, d1 * rstd * gv.y + bv.y,
           oH[(size_t)row * 256 + tid], oL[(size_t)row * 256 + tid]);
}

// ---------------------------------------------------------------- final LayerNorm (fp32, row 0)
__global__ void layernorm_kernel(const float* __restrict__ x, const float* __restrict__ g,
                                 const float* __restrict__ b, float* __restrict__ out)
{
    int tid = threadIdx.x;
    float x0 = x[tid], x1 = x[tid + 256];
    __shared__ float red[8];

    float s = x0 + x1;
#pragma unroll
    for (int o = 16; o; o >>= 1) s += __shfl_xor_sync(0xffffffffu, s, o);
    if ((tid & 31) == 0) red[tid >> 5] = s;
    __syncthreads();
    if (tid == 0) { float t = 0; for (int i = 0; i < 8; i++) t += red[i]; red[0] = t; }
    __syncthreads();
    float mu = red[0] * (1.f / 512.f);
    __syncthreads();

    float d0 = x0 - mu, d1 = x1 - mu;
    float v = d0 * d0 + d1 * d1;
#pragma unroll
    for (int o = 16; o; o >>= 1) v += __shfl_xor_sync(0xffffffffu, v, o);
    if ((tid & 31) == 0) red[tid >> 5] = v;
    __syncthreads();
    if (tid == 0) { float t = 0; for (int i = 0; i < 8; i++) t += red[i]; red[0] = t; }
    __syncthreads();
    float rstd = rsqrtf(red[0] * (1.f / 512.f) + 1e-5f);

    out[tid]       = d0 * rstd * g[tid] + b[tid];
    out[tid + 256] = d1 * rstd * g[tid + 256] + b[tid + 256];
}

// ---------------------------------------------------------------- cls attention (packed I/O)
__global__ void cls_attn_kernel(const uint* __restrict__ qvH, const uint* __restrict__ qvL,
                                uint* __restrict__ aH, uint* __restrict__ aL)
{
    int h = blockIdx.x;
    int tid = threadIdx.x;  // 256
    __shared__ float sl[NTOK];
    __shared__ float qs[DH];
    __shared__ float red[8];
    __shared__ float part[4][DH];

    if (tid < 32) {
        float2 qv = rec2(qvH[h * 32 + tid], qvL[h * 32 + tid]);
        qs[2 * tid]     = ASCALE * qv.x;
        qs[2 * tid + 1] = ASCALE * qv.y;
    }
    __syncthreads();

    float lmax = -1e30f;
    for (int j = tid; j < NTOK; j += 256) {
        size_t base = (size_t)j * 768 + 256 + h * 32;
        float s = 0.f;
#pragma unroll
        for (int dp = 0; dp < 32; dp++) {
            float2 kv = rec2(qvH[base + dp], qvL[base + dp]);
            s += qs[2 * dp] * kv.x + qs[2 * dp + 1] * kv.y;
        }
        sl[j] = s;
        lmax = fmaxf(lmax, s);
    }
#pragma unroll
    for (int o = 16; o; o >>= 1) lmax = fmaxf(lmax, __shfl_xor_sync(0xffffffffu, lmax, o));
    if ((tid & 31) == 0) red[tid >> 5] = lmax;
    __syncthreads();
    if (tid == 0) { float m = red[0]; for (int i = 1; i < 8; i++) m = fmaxf(m, red[i]); red[0] = m; }
    __syncthreads();
    float mx = red[0];
    __syncthreads();

    float lsum = 0.f;
    for (int j = tid; j < NTOK; j += 256) {
        float e = expf(sl[j] - mx);
        sl[j] = e;
        lsum += e;
    }
#pragma unroll
    for (int o = 16; o; o >>= 1) lsum += __shfl_xor_sync(0xffffffffu, lsum, o);
    if ((tid & 31) == 0) red[tid >> 5] = lsum;
    __syncthreads();
    if (tid == 0) { float t = 0; for (int i = 0; i < 8; i++) t += red[i]; red[0] = t; }
    __syncthreads();
    float inv = 1.f / red[0];
    __syncthreads();

    int gi = tid >> 6, d = tid & 63;
    int dp = d >> 1, sel = d & 1;
    float acc = 0.f;
    for (int j = gi; j < NTOK; j += 4) {
        size_t off = (size_t)j * 768 + 512 + h * 32 + dp;
        acc += sl[j] * recel(qvH[off], qvL[off], sel);
    }
    part[gi][d] = acc;
    __syncthreads();
    if (tid < 32) {
        float v0 = (part[0][2*tid]   + part[1][2*tid]   + part[2][2*tid]   + part[3][2*tid])   * inv;
        float v1 = (part[0][2*tid+1] + part[1][2*tid+1] + part[2][2*tid+1] + part[3][2*tid+1]) * inv;
        split2(v0, v1, aH[h * 32 + tid], aL[h * 32 + tid]);
    }
}

// ---------------------------------------------------------------- time attention (packed I/O)
__global__ void time_attn_kernel(const uint* __restrict__ qvH, const uint* __restrict__ qvL,
                                 uint* __restrict__ aH, uint* __restrict__ aL)
{
    int w = (blockIdx.x * blockDim.x + threadIdx.x) >> 5;
    int lane = threadIdx.x & 31;
    if (w >= NHEAD * NSP * FRAMES) return;
    int h = w / (NSP * FRAMES);
    int rem = w % (NSP * FRAMES);
    int nn = rem / FRAMES;
    int f  = rem % FRAMES;
    int qt = 1 + f * NSP + nn;

    size_t qoff = (size_t)qt * 768 + h * 32 + lane;
    float2 qv = rec2(qvH[qoff], qvL[qoff]);
    float q0 = ASCALE * qv.x, q1 = ASCALE * qv.y;

    int kt[5] = {0, 1 + nn, 1 + NSP + nn, 1 + 2 * NSP + nn, 1 + 3 * NSP + nn};
    float lg[5];
#pragma unroll
    for (int j = 0; j < 5; j++) {
        size_t off = (size_t)kt[j] * 768 + 256 + h * 32 + lane;
        float2 kv = rec2(qvH[off], qvL[off]);
        float p = q0 * kv.x + q1 * kv.y;
#pragma unroll
        for (int o = 16; o; o >>= 1) p += __shfl_xor_sync(0xffffffffu, p, o);
        lg[j] = p;
    }
    float m = lg[0];
#pragma unroll
    for (int j = 1; j < 5; j++) m = fmaxf(m, lg[j]);
    float e[5], s = 0.f;
#pragma unroll
    for (int j = 0; j < 5; j++) { e[j] = expf(lg[j] - m); s += e[j]; }
    float inv = 1.f / s;

    float o0 = 0.f, o1 = 0.f;
#pragma unroll
    for (int j = 0; j < 5; j++) {
        size_t off = (size_t)kt[j] * 768 + 512 + h * 32 + lane;
        float2 vv = rec2(qvH[off], qvL[off]);
        float p = e[j] * inv;
        o0 += p * vv.x;
        o1 += p * vv.y;
    }
    split2(o0, o1, aH[(size_t)qt * 256 + h * 32 + lane], aL[(size_t)qt * 256 + h * 32 + lane]);
}

// ---------------------------------------------------------------- space scores (MMA)
// grid (10, 10, 64), block 256. S[g][i][j] (unscaled; ASCALE applied in softmax).
__global__ __launch_bounds__(256)
void space_scores_mma(const uint* __restrict__ qvH, const uint* __restrict__ qvL,
                      float* __restrict__ S)
{
    __shared__ uint QsH[64][36], QsL[64][36];
    __shared__ uint KsH[64][36], KsL[64][36];

    int g = blockIdx.z;
    int h = g >> 3, f = (g >> 1) & 3, half = g & 1;
    int i0 = blockIdx.x * 64;
    int j0 = blockIdx.y * 64;
    int tid = threadIdx.x;
    int lane = tid & 31;
    int warp = tid >> 5;
    int grp = lane >> 2, qid = lane & 3;
    int wm = (warp & 3) * 16;
    int wn = (warp >> 2) * 32;

#pragma unroll
    for (int p = 0; p < 8; p++) {
        int idx = tid + p * 256;
        int r = idx >> 5, kp = idx & 31;
        int i = i0 + r;
        uint qh = 0, ql = 0;
        if (i < HALFN) {
            int qt = 1 + f * NSP + half * HALFN + i;
            size_t off = (size_t)qt * 768 + h * 32 + kp;
            qh = qvH[off]; ql = qvL[off];
        }
        QsH[r][kp] = qh; QsL[r][kp] = ql;
        int j = j0 + r;
        uint kh = 0, kl = 0;
        if (j < NKEY) {
            int kt = j ? (1 + f * NSP + (1 - half) * HALFN + (j - 1)) : 0;
            size_t off = (size_t)kt * 768 + 256 + h * 32 + kp;
            kh = qvH[off]; kl = qvL[off];
        }
        KsH[r][kp] = kh; KsL[r][kp] = kl;
    }
    __syncthreads();

    float acc[4][4];
#pragma unroll
    for (int nt = 0; nt < 4; nt++)
#pragma unroll
        for (int e = 0; e < 4; e++) acc[nt][e] = 0.f;

#pragma unroll
    for (int s = 0; s < 4; s++) {
        uint ah[4], al[4];
        ah[0] = QsH[wm + grp    ][s * 8 + qid    ];
        ah[1] = QsH[wm + grp + 8][s * 8 + qid    ];
        ah[2] = QsH[wm + grp    ][s * 8 + qid + 4];
        ah[3] = QsH[wm + grp + 8][s * 8 + qid + 4];
        al[0] = QsL[wm + grp    ][s * 8 + qid    ];
        al[1] = QsL[wm + grp + 8][s * 8 + qid    ];
        al[2] = QsL[wm + grp    ][s * 8 + qid + 4];
        al[3] = QsL[wm + grp + 8][s * 8 + qid + 4];
#pragma unroll
        for (int nt = 0; nt < 4; nt++) {
            int c = wn + nt * 8 + grp;
            uint bh[2], bl[2];
            bh[0] = KsH[c][s * 8 + qid];
            bh[1] = KsH[c][s * 8 + qid + 4];
            bl[0] = KsL[c][s * 8 + qid];
            bl[1] = KsL[c][s * 8 + qid + 4];
            mma_bf16(acc[nt], al, bh);
            mma_bf16(acc[nt], ah, bl);
            mma_bf16(acc[nt], ah, bh);
        }
    }

    float* Sg = S + (size_t)g * HALFN * NKEY;
#pragma unroll
    for (int e2 = 0; e2 < 2; e2++) {
        int i = i0 + wm + grp + e2 * 8;
        if (i >= HALFN) continue;
#pragma unroll
        for (int nt = 0; nt < 4; nt++) {
            int j = j0 + wn + nt * 8 + qid * 2;
            if (j < NKEY)     Sg[(size_t)i * NKEY + j]     = acc[nt][e2 * 2 + 0];
            if (j + 1 < NKEY) Sg[(size_t)i * NKEY + j + 1] = acc[nt][e2 * 2 + 1];
        }
    }
}

// ---------------------------------------------------------------- softmax rows (ASCALE fused)
__global__ void softmax_kernel(float* __restrict__ S)
{
    int row = blockIdx.x;
    float* r = S + (size_t)row * NKEY;
    int tid = threadIdx.x;  // 128
    __shared__ float red[4];

    float m = -1e30f;
    for (int j = tid; j < NKEY; j += 128) m = fmaxf(m, r[j] * ASCALE);
#pragma unroll
    for (int o = 16; o; o >>= 1) m = fmaxf(m, __shfl_xor_sync(0xffffffffu, m, o));
    if ((tid & 31) == 0) red[tid >> 5] = m;
    __syncthreads();
    if (tid == 0) { float t = red[0]; for (int i = 1; i < 4; i++) t = fmaxf(t, red[i]); red[0] = t; }
    __syncthreads();
    m = red[0];
    __syncthreads();

    float s = 0.f;
    for (int j = tid; j < NKEY; j += 128) {
        float e = expf(r[j] * ASCALE - m);
        r[j] = e;
        s += e;
    }
#pragma unroll
    for (int o = 16; o; o >>= 1) s += __shfl_xor_sync(0xffffffffu, s, o);
    if ((tid & 31) == 0) red[tid >> 5] = s;
    __syncthreads();
    if (tid == 0) { float t = 0; for (int i = 0; i < 4; i++) t += red[i]; red[0] = t; }
    __syncthreads();
    float inv = 1.f / red[0];
    for (int j = tid; j < NKEY; j += 128) r[j] *= inv;
}

// ---------------------------------------------------------------- space AV (MMA, packed out)
// grid (10, 64), block 256. out[i][d] = sum_j P[i][j] V[j][d]
__global__ __launch_bounds__(256)
void space_av_mma(const float* __restrict__ S, const uint* __restrict__ qvH,
                  const uint* __restrict__ qvL, uint* __restrict__ aH, uint* __restrict__ aL)
{
    __shared__ uint PsH[64][36], PsL[64][36];
    __shared__ uint VsH[64][36], VsL[64][36];

    int g = blockIdx.y;
    int h = g >> 3, f = (g >> 1) & 3, half = g & 1;
    int i0 = blockIdx.x * 64;
    int tid = threadIdx.x;
    int lane = tid & 31;
    int warp = tid >> 5;
    int grp = lane >> 2, qid = lane & 3;
    int wm = (warp & 3) * 16;
    int wn = (warp >> 2) * 32;

    float acc[4][4];
#pragma unroll
    for (int nt = 0; nt < 4; nt++)
#pragma unroll
        for (int e = 0; e < 4; e++) acc[nt][e] = 0.f;

    const float* Sg = S + (size_t)g * HALFN * NKEY;

    for (int jt = 0; jt < 10; jt++) {
        int j0 = jt * 64;
#pragma unroll
        for (int p = 0; p < 8; p++) {
            int idx = tid + p * 256;
            int r = idx >> 5, jp = idx & 31;
            // P tile
            int i = i0 + r, j = j0 + 2 * jp;
            float p0 = (i < HALFN && j < NKEY)     ? Sg[(size_t)i * NKEY + j]     : 0.f;
            float p1 = (i < HALFN && j + 1 < NKEY) ? Sg[(size_t)i * NKEY + j + 1] : 0.f;
            split2(p0, p1, PsH[r][jp], PsL[r][jp]);
            // V tile (transposed pack along j)
            int d = r;
            int dp = d >> 1, sel = d & 1;
            float v0 = 0.f, v1 = 0.f;
            if (j < NKEY) {
                int kt = j ? (1 + f * NSP + (1 - half) * HALFN + (j - 1)) : 0;
                size_t off = (size_t)kt * 768 + 512 + h * 32 + dp;
                v0 = recel(qvH[off], qvL[off], sel);
            }
            if (j + 1 < NKEY) {
                int kt = (j + 1) ? (1 + f * NSP + (1 - half) * HALFN + j) : 0;
                size_t off = (size_t)kt * 768 + 512 + h * 32 + dp;
                v1 = recel(qvH[off], qvL[off], sel);
            }
            split2(v0, v1, VsH[d][jp], VsL[d][jp]);
        }
        __syncthreads();

#pragma unroll
        for (int s = 0; s < 4; s++) {
            uint ah[4], al[4];
            ah[0] = PsH[wm + grp    ][s * 8 + qid    ];
            ah[1] = PsH[wm + grp + 8][s * 8 + qid    ];
            ah[2] = PsH[wm + grp    ][s * 8 + qid + 4];
            ah[3] = PsH[wm + grp + 8][s * 8 + qid + 4];
            al[0] = PsL[wm + grp    ][s * 8 + qid    ];
            al[1] = PsL[wm + grp + 8][s * 8 + qid    ];
            al[2] = PsL[wm + grp    ][s * 8 + qid + 4];
            al[3] = PsL[wm + grp + 8][s * 8 + qid + 4];
#pragma unroll
            for (int nt = 0; nt < 4; nt++) {
                int c = wn + nt * 8 + grp;
                uint bh[2], bl[2];
                bh[0] = VsH[c][s * 8 + qid];
                bh[1] = VsH[c][s * 8 + qid + 4];
                bl[0] = VsL[c][s * 8 + qid];
                bl[1] = VsL[c][s * 8 + qid + 4];
                mma_bf16(acc[nt], al, bh);
                mma_bf16(acc[nt], ah, bl);
                mma_bf16(acc[nt], ah, bh);
            }
        }
        __syncthreads();
    }

#pragma unroll
    for (int e2 = 0; e2 < 2; e2++) {
        int i = i0 + wm + grp + e2 * 8;
        if (i >= HALFN) continue;
        int qt = 1 + f * NSP + half * HALFN + i;
#pragma unroll
        for (int nt = 0; nt < 4; nt++) {
            int c = wn + nt * 8 + qid * 2;   // even
            split2(acc[nt][e2 * 2], acc[nt][e2 * 2 + 1],
                   aH[(size_t)qt * 256 + h * 32 + (c >> 1)],
                   aL[(size_t)qt * 256 + h * 32 + (c >> 1)]);
        }
    }
}

// ---------------------------------------------------------------- GEGLU (packed I/O)
__global__ void geglu_kernel(const uint* __restrict__ hH, const uint* __restrict__ hL,
                             uint* __restrict__ oH, uint* __restrict__ oL)
{
    int idx = blockIdx.x * blockDim.x + threadIdx.x;
    if (idx >= NTOK * 1024) return;
    int t = idx >> 10, i = idx & 1023;
    size_t base = (size_t)t * 2048;
    float2 uv = rec2(hH[base + i], hL[base + i]);
    float2 gv = rec2(hH[base + 1024 + i], hL[base + 1024 + i]);
    float ge0 = 0.5f * gv.x * (1.f + erff(gv.x * 0.70710678118654752f));
    float ge1 = 0.5f * gv.y * (1.f + erff(gv.y * 0.70710678118654752f));
    split2(uv.x * ge0, uv.y * ge1, oH[idx], oL[idx]);
}

// ---------------------------------------------------------------- head
__global__ void head_kernel(const float* __restrict__ xn, const float* __restrict__ ow,
                            const float* __restrict__ ob, float* __restrict__ out)
{
    int tid = threadIdx.x;
    if (tid >= 60) return;
    float s = ob[tid];
    for (int d = 0; d < D; d++) s += xn[d] * ow[d * 60 + tid];
    out[tid] = s;
}

}  // namespace

extern "C" void kernel_launch(void* const* d_in, const int* in_sizes, int n_in,
                              void* d_out, int out_size)
{
    const float* video   = (const float*)d_in[0];
    const float* patch_w = (const float*)d_in[1];
    const float* patch_b = (const float*)d_in[2];
    const float* pos_emb = (const float*)d_in[3];
    const float* cls_tok = (const float*)d_in[4];
    const float* t_ln_g  = (const float*)d_in[5];
    const float* t_ln_b  = (const float*)d_in[6];
    const float* t_qkv_w = (const float*)d_in[7];
    const float* t_out_w = (const float*)d_in[8];
    const float* t_out_b = (const float*)d_in[9];
    const float* s_ln_g  = (const float*)d_in[10];
    const float* s_ln_b  = (const float*)d_in[11];
    const float* s_qkv_w = (const float*)d_in[12];
    const float* s_out_w = (const float*)d_in[13];
    const float* s_out_b = (const float*)d_in[14];
    const float* f_ln_g  = (const float*)d_in[15];
    const float* f_ln_b  = (const float*)d_in[16];
    const float* f_w1    = (const float*)d_in[17];
    const float* f_b1    = (const float*)d_in[18];
    const float* f_w2    = (const float*)d_in[19];
    const float* f_b2    = (const float*)d_in[20];
    const float* o_ln_g  = (const float*)d_in[21];
    const float* o_ln_b  = (const float*)d_in[22];
    const float* o_w     = (const float*)d_in[23];
    const float* o_b     = (const float*)d_in[24];
    float* out = (float*)d_out;

    float *x, *xn, *S;
    cudaGetSymbolAddress((void**)&x,  g_x);
    cudaGetSymbolAddress((void**)&xn, g_xn);
    cudaGetSymbolAddress((void**)&S,  g_S);

    uint *qvH, *qvL, *hH, *hL, *xnH, *xnL, *atH, *atL, *acH, *acL, *tkH, *tkL;
    cudaGetSymbolAddress((void**)&qvH, g_qvH); cudaGetSymbolAddress((void**)&qvL, g_qvL);
    cudaGetSymbolAddress((void**)&hH,  g_hH);  cudaGetSymbolAddress((void**)&hL,  g_hL);
    cudaGetSymbolAddress((void**)&xnH, g_xnH); cudaGetSymbolAddress((void**)&xnL, g_xnL);
    cudaGetSymbolAddress((void**)&atH, g_atH); cudaGetSymbolAddress((void**)&atL, g_atL);
    cudaGetSymbolAddress((void**)&acH, g_acH); cudaGetSymbolAddress((void**)&acL, g_acL);
    cudaGetSymbolAddress((void**)&tkH, g_tkH); cudaGetSymbolAddress((void**)&tkL, g_tkL);

    uint *wqtH, *wqtL, *wqsH, *wqsL, *wotH, *wotL, *wosH, *wosL, *w1H, *w1L, *w2H, *w2L, *wpH, *wpL;
    cudaGetSymbolAddress((void**)&wqtH, g_wqtH); cudaGetSymbolAddress((void**)&wqtL, g_wqtL);
    cudaGetSymbolAddress((void**)&wqsH, g_wqsH); cudaGetSymbolAddress((void**)&wqsL, g_wqsL);
    cudaGetSymbolAddress((void**)&wotH, g_wotH); cudaGetSymbolAddress((void**)&wotL, g_wotL);
    cudaGetSymbolAddress((void**)&wosH, g_wosH); cudaGetSymbolAddress((void**)&wosL, g_wosL);
    cudaGetSymbolAddress((void**)&w1H,  g_w1H);  cudaGetSymbolAddress((void**)&w1L,  g_w1L);
    cudaGetSymbolAddress((void**)&w2H,  g_w2H);  cudaGetSymbolAddress((void**)&w2L,  g_w2L);
    cudaGetSymbolAddress((void**)&wpH,  g_wpH);  cudaGetSymbolAddress((void**)&wpL,  g_wpL);

    auto splitw = [&](const float* W, uint* H, uint* L, long long Kp_total, int N) {
        long long total = Kp_total * N;
        int blocks = (int)((total + 255) / 256);
        split_w_kernel<<<blocks, 256>>>(W, H, L, N, total);
    };

    splitw(t_qkv_w, wqtH, wqtL, 12LL * 256, QKVW);
    splitw(s_qkv_w, wqsH, wqsL, 12LL * 256, QKVW);
    splitw(t_out_w, wotH, wotL, 12LL * 256, D);
    splitw(s_out_w, wosH, wosL, 12LL * 256, D);
    splitw(f_w1,    w1H,  w1L,  12LL * 256, FF1);
    splitw(f_w2,    w2H,  w2L,  12LL * 1024, D);
    splitw(patch_w, wpH,  wpL,  384LL, D);

    auto gemmF = [&](const uint* AH, const uint* AL, const uint* BH, const uint* BL,
                     const float* bias, const float* resid, float* C, int M, int N, int Kp) {
        dim3 grid(N / 128, (M + 127) / 128);
        bgemm_kernel<false><<<grid, 256>>>(AH, AL, BH, BL, bias, resid, C, nullptr, nullptr, M, N, Kp);
    };
    auto gemmP = [&](const uint* AH, const uint* AL, const uint* BH, const uint* BL,
                     const float* bias, uint* CH, uint* CL, int M, int N, int Kp) {
        dim3 grid(N / 128, (M + 127) / 128);
        bgemm_kernel<true><<<grid, 256>>>(AH, AL, BH, BL, bias, nullptr, nullptr, CH, CL, M, N, Kp);
    };

    // ---- patch embed + pos + cls ----
    patchify_kernel<<<(NPATCH * 384 + 255) / 256, 256>>>(video, tkH, tkL);
    gemmF(tkH, tkL, wpH, wpL, patch_b, nullptr, x + D, NPATCH, D, 384);
    addpos_kernel<<<(NTOK * D + 255) / 256, 256>>>(x, cls_tok, pos_emb);

    for (int i = 0; i < 12; i++) {
        // ---------------- time attention ----------------
        layernorm_pack_kernel<<<NTOK, 256>>>(x, t_ln_g + i * D, t_ln_b + i * D, xnH, xnL);
        gemmP(xnH, xnL, wqtH + (size_t)i * 256 * QKVW, wqtL + (size_t)i * 256 * QKVW,
              nullptr, qvH, qvL, NTOK, QKVW, 256);
        cls_attn_kernel<<<NHEAD, 256>>>(qvH, qvL, atH, atL);
        time_attn_kernel<<<(NHEAD * NSP * FRAMES * 32 + 255) / 256, 256>>>(qvH, qvL, atH, atL);
        gemmF(atH, atL, wotH + (size_t)i * 256 * D, wotL + (size_t)i * 256 * D,
              t_out_b + i * D, x, x, NTOK, D, 256);

        // ---------------- space attention ----------------
        layernorm_pack_kernel<<<NTOK, 256>>>(x, s_ln_g + i * D, s_ln_b + i * D, xnH, xnL);
        gemmP(xnH, xnL, wqsH + (size_t)i * 256 * QKVW, wqsL + (size_t)i * 256 * QKVW,
              nullptr, qvH, qvL, NTOK, QKVW, 256);
        cls_attn_kernel<<<NHEAD, 256>>>(qvH, qvL, atH, atL);
        {
            dim3 gs(10, 10, NGRP);
            space_scores_mma<<<gs, 256>>>(qvH, qvL, S);
            softmax_kernel<<<NGRP * HALFN, 128>>>(S);
            dim3 ga(10, NGRP);
            space_av_mma<<<ga, 256>>>(S, qvH, qvL, atH, atL);
        }
        gemmF(atH, atL, wosH + (size_t)i * 256 * D, wosL + (size_t)i * 256 * D,
              s_out_b + i * D, x, x, NTOK, D, 256);

        // ---------------- GEGLU FF ----------------
        layernorm_pack_kernel<<<NTOK, 256>>>(x, f_ln_g + i * D, f_ln_b + i * D, xnH, xnL);
        gemmP(xnH, xnL, w1H + (size_t)i * 256 * FF1, w1L + (size_t)i * 256 * FF1,
              f_b1 + i * FF1, hH, hL, NTOK, FF1, 256);
        geglu_kernel<<<(NTOK * 1024 + 255) / 256, 256>>>(hH, hL, acH, acL);
        gemmF(acH, acL, w2H + (size_t)i * 1024 * D, w2L + (size_t)i * 1024 * D,
              f_b2 + i * D, x, x, NTOK, D, 1024);
    }

    // ---- final LN on cls + head ----
    layernorm_kernel<<<1, 256>>>(x, o_ln_g, o_ln_b, xn);
    head_kernel<<<1, 64>>>(xn, o_w, o_b, out);
}

// round 8
// speedup vs baseline: 1.2353x; 1.2353x over previous
#include <cuda_runtime.h>
#include <cuda_bf16.h>
#include <math.h>

namespace {

typedef unsigned int uint;

constexpr int NTOK  = 4801;
constexpr int D     = 512;
constexpr int QKVW  = 1536;
constexpr int NSP   = 1200;
constexpr int HALFN = 600;
constexpr int NKEY  = 601;
constexpr int NHEAD = 8;
constexpr int DH    = 64;
constexpr float ASCALE = 0.125f;
constexpr int FF1   = 4096;
constexpr int NPATCH= 4800;
constexpr int NGRP  = 64;

// fp32 buffers
__device__ float g_x  [NTOK * D];
__device__ float g_xn [D];
__device__ float g_qkv[NTOK * QKVW];
__device__ float g_h  [NTOK * FF1];
__device__ float g_S  [(size_t)NGRP * HALFN * NKEY];

// packed bf16x2 hi/lo activations (pair along k)
__device__ uint g_xnH[NTOK * 256],  g_xnL[NTOK * 256];
__device__ uint g_atH[NTOK * 256],  g_atL[NTOK * 256];
__device__ uint g_acH[NTOK * 1024], g_acL[NTOK * 1024];
__device__ uint g_tkH[NPATCH * 384], g_tkL[NPATCH * 384];

// split weights [Kp][N] packed bf16x2 (pair along k), per layer contiguous
__device__ uint g_wqtH[12 * 256 * QKVW], g_wqtL[12 * 256 * QKVW];
__device__ uint g_wqsH[12 * 256 * QKVW], g_wqsL[12 * 256 * QKVW];
__device__ uint g_wotH[12 * 256 * D],    g_wotL[12 * 256 * D];
__device__ uint g_wosH[12 * 256 * D],    g_wosL[12 * 256 * D];
__device__ uint g_w1H [12 * 256 * FF1],  g_w1L [12 * 256 * FF1];
__device__ uint g_w2H [12 * 1024 * D],   g_w2L [12 * 1024 * D];
__device__ uint g_wpH [384 * D],         g_wpL [384 * D];

__device__ __forceinline__ void split2(float x0, float x1, uint& hi, uint& lo) {
    __nv_bfloat16 h0 = __float2bfloat16(x0);
    __nv_bfloat16 h1 = __float2bfloat16(x1);
    __nv_bfloat16 l0 = __float2bfloat16(x0 - __bfloat162float(h0));
    __nv_bfloat16 l1 = __float2bfloat16(x1 - __bfloat162float(h1));
    __nv_bfloat162 H = __nv_bfloat162(h0, h1);
    __nv_bfloat162 L = __nv_bfloat162(l0, l1);
    hi = *reinterpret_cast<uint*>(&H);
    lo = *reinterpret_cast<uint*>(&L);
}

__device__ __forceinline__ void mma_bf16(float* acc, const uint* a, const uint* b) {
    asm volatile(
        "mma.sync.aligned.m16n8k16.row.col.f32.bf16.bf16.f32 "
        "{%0,%1,%2,%3}, {%4,%5,%6,%7}, {%8,%9}, {%0,%1,%2,%3};"
        : "+f"(acc[0]), "+f"(acc[1]), "+f"(acc[2]), "+f"(acc[3])
        : "r"(a[0]), "r"(a[1]), "r"(a[2]), "r"(a[3]), "r"(b[0]), "r"(b[1]));
}

__device__ __forceinline__ uint smem_u32(const void* p) {
    uint a;
    asm("{ .reg .u64 t; cvta.to.shared.u64 t, %1; cvt.u32.u64 %0, t; }" : "=r"(a) : "l"(p));
    return a;
}

// stage layout (uints): AsH[128*20]=2560, AsL=2560, BsH[16*136]=2176, BsL=2176  -> 9472/stage
constexpr int STG_U   = 9472;
constexpr int OFF_AL  = 2560;
constexpr int OFF_BH  = 5120;
constexpr int OFF_BL  = 7296;
constexpr int SMEM_G  = 2 * STG_U * 4;   // 75776 bytes

// ---------------------------------------------------------------- split-bf16 GEMM (cp.async pipelined)
// C[M,N] = A[M,K] @ B[K,N] (+bias)(+resid). K=2*Kp.
// A: (AH,AL)[M][Kp] packed bf16x2 k-major. B: (BH,BL)[Kp][N] packed.
// BM=128 BN=128, K-step 32 (16 pairs). 256 threads, 8 warps, warp tile 64x32, 3-term hi/lo.
__global__ __launch_bounds__(256, 2)
void bgemm_kernel(const uint* __restrict__ AH, const uint* __restrict__ AL,
                  const uint* __restrict__ BH, const uint* __restrict__ BL,
                  const float* __restrict__ bias, const float* __restrict__ resid,
                  float* __restrict__ C, int M, int N, int Kp)
{
    extern __shared__ uint dsm[];
    const uint sbase = smem_u32(dsm);
    const int tid  = threadIdx.x;
    const int lane = tid & 31;
    const int warp = tid >> 5;
    const int grp  = lane >> 2;
    const int qid  = lane & 3;
    const int wm   = (warp & 1) * 64;
    const int wn   = (warp >> 1) * 32;
    const int row0 = blockIdx.y * 128;
    const int col0 = blockIdx.x * 128;

    float acc[4][4][4];
#pragma unroll
    for (int mt = 0; mt < 4; mt++)
#pragma unroll
        for (int nt = 0; nt < 4; nt++)
#pragma unroll
            for (int e = 0; e < 4; e++) acc[mt][nt][e] = 0.f;

    auto load_stage = [&](int st, int kp0) {
        uint base = sbase + st * (STG_U * 4);
        // A: 128 rows x 4 16B chunks, hi+lo
#pragma unroll
        for (int u = 0; u < 2; u++) {
            int idx = tid + u * 256;
            int r = idx >> 2, c4 = idx & 3;
            int gr = row0 + r;
            int sz = (gr < M) ? 16 : 0;
            size_t goff = (size_t)(gr < M ? gr : 0) * Kp + kp0 + c4 * 4;
            uint d = base + (r * 20 + c4 * 4) * 4;
            asm volatile("cp.async.cg.shared.global [%0], [%1], 16, %2;"
                         :: "r"(d), "l"(AH + goff), "r"(sz));
            asm volatile("cp.async.cg.shared.global [%0], [%1], 16, %2;"
                         :: "r"(d + OFF_AL * 4), "l"(AL + goff), "r"(sz));
        }
        // B: 16 kp-rows x 32 16B chunks, hi+lo
#pragma unroll
        for (int u = 0; u < 2; u++) {
            int idx = tid + u * 256;
            int kr = idx >> 5, c4 = idx & 31;
            size_t goff = (size_t)(kp0 + kr) * N + col0 + c4 * 4;
            uint d = base + (OFF_BH + kr * 136 + c4 * 4) * 4;
            asm volatile("cp.async.cg.shared.global [%0], [%1], 16;"
                         :: "r"(d), "l"(BH + goff));
            asm volatile("cp.async.cg.shared.global [%0], [%1], 16;"
                         :: "r"(d + (OFF_BL - OFF_BH) * 4), "l"(BL + goff));
        }
    };

    auto compute = [&](int st) {
        const uint* AsH = dsm + st * STG_U;
        const uint* AsL = AsH + OFF_AL;
        const uint* BsH = dsm + st * STG_U + OFF_BH;
        const uint* BsL = dsm + st * STG_U + OFF_BL;
#pragma unroll
        for (int kk = 0; kk < 2; kk++) {
            uint bhf[4][2], blf[4][2];
#pragma unroll
            for (int nt = 0; nt < 4; nt++) {
                int c = wn + nt * 8 + grp;
                bhf[nt][0] = BsH[(kk * 8 + qid    ) * 136 + c];
                bhf[nt][1] = BsH[(kk * 8 + qid + 4) * 136 + c];
                blf[nt][0] = BsL[(kk * 8 + qid    ) * 136 + c];
                blf[nt][1] = BsL[(kk * 8 + qid + 4) * 136 + c];
            }
#pragma unroll
            for (int mt = 0; mt < 4; mt++) {
                int r = wm + mt * 16;
                uint ah[4], al[4];
                ah[0] = AsH[(r + grp    ) * 20 + kk * 8 + qid    ];
                ah[1] = AsH[(r + grp + 8) * 20 + kk * 8 + qid    ];
                ah[2] = AsH[(r + grp    ) * 20 + kk * 8 + qid + 4];
                ah[3] = AsH[(r + grp + 8) * 20 + kk * 8 + qid + 4];
                al[0] = AsL[(r + grp    ) * 20 + kk * 8 + qid    ];
                al[1] = AsL[(r + grp + 8) * 20 + kk * 8 + qid    ];
                al[2] = AsL[(r + grp    ) * 20 + kk * 8 + qid + 4];
                al[3] = AsL[(r + grp + 8) * 20 + kk * 8 + qid + 4];
#pragma unroll
                for (int nt = 0; nt < 4; nt++) {
                    mma_bf16(acc[mt][nt], al, bhf[nt]);
                    mma_bf16(acc[mt][nt], ah, blf[nt]);
                    mma_bf16(acc[mt][nt], ah, bhf[nt]);
                }
            }
        }
    };

    const int nch = Kp / 16;
    load_stage(0, 0);
    asm volatile("cp.async.commit_group;" ::: "memory");
    for (int ch = 0; ch < nch; ch++) {
        if (ch + 1 < nch) {
            load_stage((ch + 1) & 1, (ch + 1) * 16);
            asm volatile("cp.async.commit_group;" ::: "memory");
            asm volatile("cp.async.wait_group 1;" ::: "memory");
        } else {
            asm volatile("cp.async.wait_group 0;" ::: "memory");
        }
        __syncthreads();
        compute(ch & 1);
        __syncthreads();
    }

#pragma unroll
    for (int mt = 0; mt < 4; mt++) {
#pragma unroll
        for (int e2 = 0; e2 < 2; e2++) {
            int gr = row0 + wm + mt * 16 + grp + e2 * 8;
            if (gr >= M) continue;
#pragma unroll
            for (int nt = 0; nt < 4; nt++) {
                int gc = col0 + wn + nt * 8 + qid * 2;
                float v0 = acc[mt][nt][e2 * 2 + 0];
                float v1 = acc[mt][nt][e2 * 2 + 1];
                if (bias)  { v0 += bias[gc]; v1 += bias[gc + 1]; }
                if (resid) {
                    v0 += resid[(size_t)gr * N + gc];
                    v1 += resid[(size_t)gr * N + gc + 1];
                }
                C[(size_t)gr * N + gc]     = v0;
                C[(size_t)gr * N + gc + 1] = v1;
            }
        }
    }
}

// ---------------------------------------------------------------- weight split prep
// W:[2*Kp][N] fp32 -> H/L:[Kp][N] packed bf16x2 (pair along k)
__global__ void split_w_kernel(const float* __restrict__ W, uint* __restrict__ H,
                               uint* __restrict__ L, int N, long long total)
{
    long long idx = (long long)blockIdx.x * blockDim.x + threadIdx.x;
    if (idx >= total) return;
    long long kp = idx / N;
    int n = (int)(idx - kp * N);
    float x0 = W[(size_t)(2 * kp) * N + n];
    float x1 = W[(size_t)(2 * kp + 1) * N + n];
    split2(x0, x1, H[idx], L[idx]);
}

// ---------------------------------------------------------------- patchify (packed out)
__global__ void patchify_kernel(const float* __restrict__ video,
                                uint* __restrict__ tH, uint* __restrict__ tL)
{
    int idx = blockIdx.x * blockDim.x + threadIdx.x;
    if (idx >= NPATCH * 384) return;
    int t = idx / 384, pp = idx % 384;
    int side = t / 2400;
    int r = t % 2400;
    int f = r / 600;
    int rr = r % 600;
    int ph = rr / 20;
    int pw = rr % 20;
    float v[2];
#pragma unroll
    for (int e = 0; e < 2; e++) {
        int pd = pp * 2 + e;
        int p1 = pd / 48;
        int rem = pd % 48;
        int p2 = rem / 3;
        int c  = rem % 3;
        int row = ph * 16 + p1;
        int col = side * 320 + pw * 16 + p2;
        v[e] = video[(((size_t)f * 3 + c) * 480 + row) * 640 + col];
    }
    split2(v[0], v[1], tH[idx], tL[idx]);
}

__global__ void addpos_kernel(float* __restrict__ x, const float* __restrict__ cls,
                              const float* __restrict__ pos)
{
    int idx = blockIdx.x * blockDim.x + threadIdx.x;
    if (idx >= NTOK * D) return;
    if (idx < D) x[idx] = cls[idx] + pos[idx];
    else         x[idx] += pos[idx];
}

// ---------------------------------------------------------------- LayerNorm (packed out)
__global__ void layernorm_pack_kernel(const float* __restrict__ x, const float* __restrict__ g,
                                      const float* __restrict__ b,
                                      uint* __restrict__ oH, uint* __restrict__ oL)
{
    int row = blockIdx.x;
    int tid = threadIdx.x;  // 256
    const float* xr = x + (size_t)row * D;
    float2 xv = *reinterpret_cast<const float2*>(xr + 2 * tid);
    __shared__ float red[8];

    float s = xv.x + xv.y;
#pragma unroll
    for (int o = 16; o; o >>= 1) s += __shfl_xor_sync(0xffffffffu, s, o);
    if ((tid & 31) == 0) red[tid >> 5] = s;
    __syncthreads();
    if (tid == 0) { float t = 0; for (int i = 0; i < 8; i++) t += red[i]; red[0] = t; }
    __syncthreads();
    float mu = red[0] * (1.f / 512.f);
    __syncthreads();

    float d0 = xv.x - mu, d1 = xv.y - mu;
    float v = d0 * d0 + d1 * d1;
#pragma unroll
    for (int o = 16; o; o >>= 1) v += __shfl_xor_sync(0xffffffffu, v, o);
    if ((tid & 31) == 0) red[tid >> 5] = v;
    __syncthreads();
    if (tid == 0) { float t = 0; for (int i = 0; i < 8; i++) t += red[i]; red[0] = t; }
    __syncthreads();
    float rstd = rsqrtf(red[0] * (1.f / 512.f) + 1e-5f);

    float2 gv = *reinterpret_cast<const float2*>(g + 2 * tid);
    float2 bv = *reinterpret_cast<const float2*>(b + 2 * tid);
    split2(d0 * rstd * gv.x + bv.x, d1 * rstd * gv.y + bv.y,
           oH[(size_t)row * 256 + tid], oL[(size_t)row * 256 + tid]);
}

// ---------------------------------------------------------------- final LN (fp32, row 0)
__global__ void layernorm_kernel(const float* __restrict__ x, const float* __restrict__ g,
                                 const float* __restrict__ b, float* __restrict__ out)
{
    int tid = threadIdx.x;
    float x0 = x[tid], x1 = x[tid + 256];
    __shared__ float red[8];

    float s = x0 + x1;
#pragma unroll
    for (int o = 16; o; o >>= 1) s += __shfl_xor_sync(0xffffffffu, s, o);
    if ((tid & 31) == 0) red[tid >> 5] = s;
    __syncthreads();
    if (tid == 0) { float t = 0; for (int i = 0; i < 8; i++) t += red[i]; red[0] = t; }
    __syncthreads();
    float mu = red[0] * (1.f / 512.f);
    __syncthreads();

    float d0 = x0 - mu, d1 = x1 - mu;
    float v = d0 * d0 + d1 * d1;
#pragma unroll
    for (int o = 16; o; o >>= 1) v += __shfl_xor_sync(0xffffffffu, v, o);
    if ((tid & 31) == 0) red[tid >> 5] = v;
    __syncthreads();
    if (tid == 0) { float t = 0; for (int i = 0; i < 8; i++) t += red[i]; red[0] = t; }
    __syncthreads();
    float rstd = rsqrtf(red[0] * (1.f / 512.f) + 1e-5f);

    out[tid]       = d0 * rstd * g[tid] + b[tid];
    out[tid + 256] = d1 * rstd * g[tid + 256] + b[tid + 256];
}

// ---------------------------------------------------------------- cls attention (fp32 in, packed out)
__global__ void cls_attn_kernel(const float* __restrict__ qkv,
                                uint* __restrict__ aH, uint* __restrict__ aL)
{
    int h = blockIdx.x;
    int tid = threadIdx.x;  // 256
    __shared__ float sl[NTOK];
    __shared__ float qs[DH];
    __shared__ float red[8];
    __shared__ float part[4][DH];

    if (tid < DH) qs[tid] = ASCALE * qkv[h * DH + tid];
    __syncthreads();

    float lmax = -1e30f;
    for (int j = tid; j < NTOK; j += 256) {
        const float* kb = qkv + (size_t)j * QKVW + 512 + h * DH;
        float s = 0.f;
#pragma unroll
        for (int d = 0; d < DH; d++) s += qs[d] * kb[d];
        sl[j] = s;
        lmax = fmaxf(lmax, s);
    }
#pragma unroll
    for (int o = 16; o; o >>= 1) lmax = fmaxf(lmax, __shfl_xor_sync(0xffffffffu, lmax, o));
    if ((tid & 31) == 0) red[tid >> 5] = lmax;
    __syncthreads();
    if (tid == 0) { float m = red[0]; for (int i = 1; i < 8; i++) m = fmaxf(m, red[i]); red[0] = m; }
    __syncthreads();
    float mx = red[0];
    __syncthreads();

    float lsum = 0.f;
    for (int j = tid; j < NTOK; j += 256) {
        float e = expf(sl[j] - mx);
        sl[j] = e;
        lsum += e;
    }
#pragma unroll
    for (int o = 16; o; o >>= 1) lsum += __shfl_xor_sync(0xffffffffu, lsum, o);
    if ((tid & 31) == 0) red[tid >> 5] = lsum;
    __syncthreads();
    if (tid == 0) { float t = 0; for (int i = 0; i < 8; i++) t += red[i]; red[0] = t; }
    __syncthreads();
    float inv = 1.f / red[0];
    __syncthreads();

    int gi = tid >> 6, d = tid & 63;
    float acc = 0.f;
    for (int j = gi; j < NTOK; j += 4)
        acc += sl[j] * qkv[(size_t)j * QKVW + 1024 + h * DH + d];
    part[gi][d] = acc;
    __syncthreads();
    if (tid < 32) {
        float v0 = (part[0][2*tid]   + part[1][2*tid]   + part[2][2*tid]   + part[3][2*tid])   * inv;
        float v1 = (part[0][2*tid+1] + part[1][2*tid+1] + part[2][2*tid+1] + part[3][2*tid+1]) * inv;
        split2(v0, v1, aH[h * 32 + tid], aL[h * 32 + tid]);
    }
}

// ---------------------------------------------------------------- time attention (fp32 in, packed out)
__global__ void time_attn_kernel(const float* __restrict__ qkv,
                                 uint* __restrict__ aH, uint* __restrict__ aL)
{
    int w = (blockIdx.x * blockDim.x + threadIdx.x) >> 5;
    int lane = threadIdx.x & 31;
    if (w >= NHEAD * NSP * 4) return;
    int h = w / (NSP * 4);
    int rem = w % (NSP * 4);
    int nn = rem / 4;
    int f  = rem % 4;
    int qt = 1 + f * NSP + nn;

    const float* qb = qkv + (size_t)qt * QKVW + h * DH;
    float q0 = ASCALE * qb[2 * lane], q1 = ASCALE * qb[2 * lane + 1];

    int kt[5] = {0, 1 + nn, 1 + NSP + nn, 1 + 2 * NSP + nn, 1 + 3 * NSP + nn};
    float lg[5];
#pragma unroll
    for (int j = 0; j < 5; j++) {
        const float* kb = qkv + (size_t)kt[j] * QKVW + 512 + h * DH;
        float p = q0 * kb[2 * lane] + q1 * kb[2 * lane + 1];
#pragma unroll
        for (int o = 16; o; o >>= 1) p += __shfl_xor_sync(0xffffffffu, p, o);
        lg[j] = p;
    }
    float m = lg[0];
#pragma unroll
    for (int j = 1; j < 5; j++) m = fmaxf(m, lg[j]);
    float e[5], s = 0.f;
#pragma unroll
    for (int j = 0; j < 5; j++) { e[j] = expf(lg[j] - m); s += e[j]; }
    float inv = 1.f / s;

    float o0 = 0.f, o1 = 0.f;
#pragma unroll
    for (int j = 0; j < 5; j++) {
        const float* vb = qkv + (size_t)kt[j] * QKVW + 1024 + h * DH;
        float p = e[j] * inv;
        o0 += p * vb[2 * lane];
        o1 += p * vb[2 * lane + 1];
    }
    split2(o0, o1, aH[(size_t)qt * 256 + h * 32 + lane], aL[(size_t)qt * 256 + h * 32 + lane]);
}

// ---------------------------------------------------------------- space scores (SIMT fp32)
__global__ void space_scores_kernel(const float* __restrict__ qkv, float* __restrict__ S)
{
    int g = blockIdx.z;
    int h = g >> 3, f = (g >> 1) & 3, half = g & 1;
    int i0 = blockIdx.x * 64;
    int j0 = blockIdx.y * 64;
    int tid = threadIdx.x;
    int tx = tid & 15, ty = tid >> 4;

    __shared__ float Qs[64][65];
    __shared__ float Ks[64][65];

#pragma unroll
    for (int u = 0; u < 16; u++) {
        int idx = tid + u * 256;
        int r = idx >> 6, d = idx & 63;
        int i = i0 + r;
        float v = 0.f;
        if (i < HALFN) {
            int qt = 1 + f * NSP + half * HALFN + i;
            v = ASCALE * qkv[(size_t)qt * QKVW + h * DH + d];
        }
        Qs[r][d] = v;
    }
#pragma unroll
    for (int u = 0; u < 16; u++) {
        int idx = tid + u * 256;
        int r = idx >> 6, d = idx & 63;
        int j = j0 + r;
        float v = 0.f;
        if (j < NKEY) {
            int kt = (j == 0) ? 0 : 1 + f * NSP + (1 - half) * HALFN + (j - 1);
            v = qkv[(size_t)kt * QKVW + 512 + h * DH + d];
        }
        Ks[r][d] = v;
    }
    __syncthreads();

    float acc[4][4];
#pragma unroll
    for (int a = 0; a < 4; a++)
#pragma unroll
        for (int b = 0; b < 4; b++) acc[a][b] = 0.f;

#pragma unroll
    for (int k = 0; k < 64; k++) {
        float ra[4], rb[4];
#pragma unroll
        for (int a = 0; a < 4; a++) ra[a] = Qs[ty * 4 + a][k];
#pragma unroll
        for (int b = 0; b < 4; b++) rb[b] = Ks[tx * 4 + b][k];
#pragma unroll
        for (int a = 0; a < 4; a++)
#pragma unroll
            for (int b = 0; b < 4; b++) acc[a][b] += ra[a] * rb[b];
    }

#pragma unroll
    for (int a = 0; a < 4; a++) {
        int i = i0 + ty * 4 + a;
        if (i >= HALFN) continue;
#pragma unroll
        for (int b = 0; b < 4; b++) {
            int j = j0 + tx * 4 + b;
            if (j >= NKEY) continue;
            S[(size_t)g * HALFN * NKEY + (size_t)i * NKEY + j] = acc[a][b];
        }
    }
}

// ---------------------------------------------------------------- softmax rows
__global__ void softmax_kernel(float* __restrict__ S)
{
    int row = blockIdx.x;
    float* r = S + (size_t)row * NKEY;
    int tid = threadIdx.x;  // 128
    __shared__ float red[4];

    float m = -1e30f;
    for (int j = tid; j < NKEY; j += 128) m = fmaxf(m, r[j]);
#pragma unroll
    for (int o = 16; o; o >>= 1) m = fmaxf(m, __shfl_xor_sync(0xffffffffu, m, o));
    if ((tid & 31) == 0) red[tid >> 5] = m;
    __syncthreads();
    if (tid == 0) { float t = red[0]; for (int i = 1; i < 4; i++) t = fmaxf(t, red[i]); red[0] = t; }
    __syncthreads();
    m = red[0];
    __syncthreads();

    float s = 0.f;
    for (int j = tid; j < NKEY; j += 128) {
        float e = expf(r[j] - m);
        r[j] = e;
        s += e;
    }
#pragma unroll
    for (int o = 16; o; o >>= 1) s += __shfl_xor_sync(0xffffffffu, s, o);
    if ((tid & 31) == 0) red[tid >> 5] = s;
    __syncthreads();
    if (tid == 0) { float t = 0; for (int i = 0; i < 4; i++) t += red[i]; red[0] = t; }
    __syncthreads();
    float inv = 1.f / red[0];
    for (int j = tid; j < NKEY; j += 128) r[j] *= inv;
}

// ---------------------------------------------------------------- space AV (SIMT fp32, packed out)
__global__ void space_av_kernel(const float* __restrict__ S, const float* __restrict__ qkv,
                                uint* __restrict__ aH, uint* __restrict__ aL)
{
    int g = blockIdx.z;
    int h = g >> 3, f = (g >> 1) & 3, half = g & 1;
    int i0 = blockIdx.x * 64;
    int tid = threadIdx.x;
    int tx = tid & 15, ty = tid >> 4;

    __shared__ float Ps[64][65];
    __shared__ float Vs[64][65];

    float acc[4][4];
#pragma unroll
    for (int a = 0; a < 4; a++)
#pragma unroll
        for (int b = 0; b < 4; b++) acc[a][b] = 0.f;

    const float* Srow = S + (size_t)g * HALFN * NKEY;

    for (int j0 = 0; j0 < NKEY; j0 += 64) {
#pragma unroll
        for (int u = 0; u < 16; u++) {
            int idx = tid + u * 256;
            int rr = idx >> 6, cc = idx & 63;
            int i = i0 + rr, j = j0 + cc;
            Ps[rr][cc] = (i < HALFN && j < NKEY) ? Srow[(size_t)i * NKEY + j] : 0.f;
        }
#pragma unroll
        for (int u = 0; u < 16; u++) {
            int idx = tid + u * 256;
            int rr = idx >> 6, dd = idx & 63;
            int j = j0 + rr;
            float v = 0.f;
            if (j < NKEY) {
                int kt = (j == 0) ? 0 : 1 + f * NSP + (1 - half) * HALFN + (j - 1);
                v = qkv[(size_t)kt * QKVW + 1024 + h * DH + dd];
            }
            Vs[rr][dd] = v;
        }
        __syncthreads();
#pragma unroll
        for (int k = 0; k < 64; k++) {
            float ra[4], rb[4];
#pragma unroll
            for (int a = 0; a < 4; a++) ra[a] = Ps[ty * 4 + a][k];
#pragma unroll
            for (int b = 0; b < 4; b++) rb[b] = Vs[k][tx * 4 + b];
#pragma unroll
            for (int a = 0; a < 4; a++)
#pragma unroll
                for (int b = 0; b < 4; b++) acc[a][b] += ra[a] * rb[b];
        }
        __syncthreads();
    }

#pragma unroll
    for (int a = 0; a < 4; a++) {
        int i = i0 + ty * 4 + a;
        if (i >= HALFN) continue;
        int qt = 1 + f * NSP + half * HALFN + i;
        int base = h * 32 + tx * 2;
        split2(acc[a][0], acc[a][1], aH[(size_t)qt * 256 + base],     aL[(size_t)qt * 256 + base]);
        split2(acc[a][2], acc[a][3], aH[(size_t)qt * 256 + base + 1], aL[(size_t)qt * 256 + base + 1]);
    }
}

// ---------------------------------------------------------------- GEGLU (fp32 in, packed out)
__global__ void geglu_kernel(const float* __restrict__ h,
                             uint* __restrict__ oH, uint* __restrict__ oL)
{
    int idx = blockIdx.x * blockDim.x + threadIdx.x;
    if (idx >= NTOK * 1024) return;
    int t = idx >> 10, i = idx & 1023;
    const float* hr = h + (size_t)t * FF1;
    float2 uv = *reinterpret_cast<const float2*>(hr + 2 * i);
    float2 gv = *reinterpret_cast<const float2*>(hr + 2048 + 2 * i);
    float ge0 = 0.5f * gv.x * (1.f + erff(gv.x * 0.70710678118654752f));
    float ge1 = 0.5f * gv.y * (1.f + erff(gv.y * 0.70710678118654752f));
    split2(uv.x * ge0, uv.y * ge1, oH[idx], oL[idx]);
}

// ---------------------------------------------------------------- head
__global__ void head_kernel(const float* __restrict__ xn, const float* __restrict__ ow,
                            const float* __restrict__ ob, float* __restrict__ out)
{
    int tid = threadIdx.x;
    if (tid >= 60) return;
    float s = ob[tid];
    for (int d = 0; d < D; d++) s += xn[d] * ow[d * 60 + tid];
    out[tid] = s;
}

}  // namespace

extern "C" void kernel_launch(void* const* d_in, const int* in_sizes, int n_in,
                              void* d_out, int out_size)
{
    const float* video   = (const float*)d_in[0];
    const float* patch_w = (const float*)d_in[1];
    const float* patch_b = (const float*)d_in[2];
    const float* pos_emb = (const float*)d_in[3];
    const float* cls_tok = (const float*)d_in[4];
    const float* t_ln_g  = (const float*)d_in[5];
    const float* t_ln_b  = (const float*)d_in[6];
    const float* t_qkv_w = (const float*)d_in[7];
    const float* t_out_w = (const float*)d_in[8];
    const float* t_out_b = (const float*)d_in[9];
    const float* s_ln_g  = (const float*)d_in[10];
    const float* s_ln_b  = (const float*)d_in[11];
    const float* s_qkv_w = (const float*)d_in[12];
    const float* s_out_w = (const float*)d_in[13];
    const float* s_out_b = (const float*)d_in[14];
    const float* f_ln_g  = (const float*)d_in[15];
    const float* f_ln_b  = (const float*)d_in[16];
    const float* f_w1    = (const float*)d_in[17];
    const float* f_b1    = (const float*)d_in[18];
    const float* f_w2    = (const float*)d_in[19];
    const float* f_b2    = (const float*)d_in[20];
    const float* o_ln_g  = (const float*)d_in[21];
    const float* o_ln_b  = (const float*)d_in[22];
    const float* o_w     = (const float*)d_in[23];
    const float* o_b     = (const float*)d_in[24];
    float* out = (float*)d_out;

    cudaFuncSetAttribute(bgemm_kernel, cudaFuncAttributeMaxDynamicSharedMemorySize, SMEM_G);

    float *x, *xn, *qkv, *hbuf, *S;
    cudaGetSymbolAddress((void**)&x,    g_x);
    cudaGetSymbolAddress((void**)&xn,   g_xn);
    cudaGetSymbolAddress((void**)&qkv,  g_qkv);
    cudaGetSymbolAddress((void**)&hbuf, g_h);
    cudaGetSymbolAddress((void**)&S,    g_S);

    uint *xnH, *xnL, *atH, *atL, *acH, *acL, *tkH, *tkL;
    cudaGetSymbolAddress((void**)&xnH, g_xnH); cudaGetSymbolAddress((void**)&xnL, g_xnL);
    cudaGetSymbolAddress((void**)&atH, g_atH); cudaGetSymbolAddress((void**)&atL, g_atL);
    cudaGetSymbolAddress((void**)&acH, g_acH); cudaGetSymbolAddress((void**)&acL, g_acL);
    cudaGetSymbolAddress((void**)&tkH, g_tkH); cudaGetSymbolAddress((void**)&tkL, g_tkL);

    uint *wqtH, *wqtL, *wqsH, *wqsL, *wotH, *wotL, *wosH, *wosL, *w1H, *w1L, *w2H, *w2L, *wpH, *wpL;
    cudaGetSymbolAddress((void**)&wqtH, g_wqtH); cudaGetSymbolAddress((void**)&wqtL, g_wqtL);
    cudaGetSymbolAddress((void**)&wqsH, g_wqsH); cudaGetSymbolAddress((void**)&wqsL, g_wqsL);
    cudaGetSymbolAddress((void**)&wotH, g_wotH); cudaGetSymbolAddress((void**)&wotL, g_wotL);
    cudaGetSymbolAddress((void**)&wosH, g_wosH); cudaGetSymbolAddress((void**)&wosL, g_wosL);
    cudaGetSymbolAddress((void**)&w1H,  g_w1H);  cudaGetSymbolAddress((void**)&w1L,  g_w1L);
    cudaGetSymbolAddress((void**)&w2H,  g_w2H);  cudaGetSymbolAddress((void**)&w2L,  g_w2L);
    cudaGetSymbolAddress((void**)&wpH,  g_wpH);  cudaGetSymbolAddress((void**)&wpL,  g_wpL);

    auto splitw = [&](const float* W, uint* H, uint* L, long long Kp_total, int N) {
        long long total = Kp_total * N;
        int blocks = (int)((total + 255) / 256);
        split_w_kernel<<<blocks, 256>>>(W, H, L, N, total);
    };

    splitw(t_qkv_w, wqtH, wqtL, 12LL * 256, QKVW);
    splitw(s_qkv_w, wqsH, wqsL, 12LL * 256, QKVW);
    splitw(t_out_w, wotH, wotL, 12LL * 256, D);
    splitw(s_out_w, wosH, wosL, 12LL * 256, D);
    splitw(f_w1,    w1H,  w1L,  12LL * 256, FF1);
    splitw(f_w2,    w2H,  w2L,  12LL * 1024, D);
    splitw(patch_w, wpH,  wpL,  384LL, D);

    auto gemm = [&](const uint* AH, const uint* AL, const uint* BH, const uint* BL,
                    const float* bias, const float* resid, float* C, int M, int N, int Kp) {
        dim3 grid(N / 128, (M + 127) / 128);
        bgemm_kernel<<<grid, 256, SMEM_G>>>(AH, AL, BH, BL, bias, resid, C, M, N, Kp);
    };

    // ---- patch embed + pos + cls ----
    patchify_kernel<<<(NPATCH * 384 + 255) / 256, 256>>>(video, tkH, tkL);
    gemm(tkH, tkL, wpH, wpL, patch_b, nullptr, x + D, NPATCH, D, 384);
    addpos_kernel<<<(NTOK * D + 255) / 256, 256>>>(x, cls_tok, pos_emb);

    for (int i = 0; i < 12; i++) {
        // ---------------- time attention ----------------
        layernorm_pack_kernel<<<NTOK, 256>>>(x, t_ln_g + i * D, t_ln_b + i * D, xnH, xnL);
        gemm(xnH, xnL, wqtH + (size_t)i * 256 * QKVW, wqtL + (size_t)i * 256 * QKVW,
             nullptr, nullptr, qkv, NTOK, QKVW, 256);
        cls_attn_kernel<<<NHEAD, 256>>>(qkv, atH, atL);
        time_attn_kernel<<<(NHEAD * NSP * 4 * 32 + 255) / 256, 256>>>(qkv, atH, atL);
        gemm(atH, atL, wotH + (size_t)i * 256 * D, wotL + (size_t)i * 256 * D,
             t_out_b + i * D, x, x, NTOK, D, 256);

        // ---------------- space attention ----------------
        layernorm_pack_kernel<<<NTOK, 256>>>(x, s_ln_g + i * D, s_ln_b + i * D, xnH, xnL);
        gemm(xnH, xnL, wqsH + (size_t)i * 256 * QKVW, wqsL + (size_t)i * 256 * QKVW,
             nullptr, nullptr, qkv, NTOK, QKVW, 256);
        cls_attn_kernel<<<NHEAD, 256>>>(qkv, atH, atL);
        {
            dim3 gs((HALFN + 63) / 64, (NKEY + 63) / 64, NGRP);
            space_scores_kernel<<<gs, 256>>>(qkv, S);
            softmax_kernel<<<NGRP * HALFN, 128>>>(S);
            dim3 ga((HALFN + 63) / 64, 1, NGRP);
            space_av_kernel<<<ga, 256>>>(S, qkv, atH, atL);
        }
        gemm(atH, atL, wosH + (size_t)i * 256 * D, wosL + (size_t)i * 256 * D,
             s_out_b + i * D, x, x, NTOK, D, 256);

        // ---------------- GEGLU FF ----------------
        layernorm_pack_kernel<<<NTOK, 256>>>(x, f_ln_g + i * D, f_ln_b + i * D, xnH, xnL);
        gemm(xnH, xnL, w1H + (size_t)i * 256 * FF1, w1L + (size_t)i * 256 * FF1,
             f_b1 + i * FF1, nullptr, hbuf, NTOK, FF1, 256);
        geglu_kernel<<<(NTOK * 1024 + 255) / 256, 256>>>(hbuf, acH, acL);
        gemm(acH, acL, w2H + (size_t)i * 1024 * D, w2L + (size_t)i * 1024 * D,
             f_b2 + i * D, x, x, NTOK, D, 1024);
    }

    // ---- final LN on cls + head ----
    layernorm_kernel<<<1, 256>>>(x, o_ln_g, o_ln_b, xn);
    head_kernel<<<1, 64>>>(xn, o_w, o_b, out);
}